// round 5
// baseline (speedup 1.0000x reference)
#include <cuda_runtime.h>
#include <cstddef>

#define ALPHA_ 0.0001f
#define NN 16
#define TT 8
#define VV 256
#define FF 64
#define NVV (NN*VV*VV)
#define YTS 68              // column-tile row stride (floats): 272B, 16B-aligned, conflict-free
#define NBLK 128

__device__ float g_sloss[NBLK];
__device__ float g_dloss[NN];
__device__ unsigned int g_counter = 0;

typedef unsigned long long u64;

__device__ __forceinline__ u64 addx2(u64 a, u64 b) {
    u64 r;
    asm("add.rn.f32x2 %0, %1, %2;" : "=l"(r) : "l"(a), "l"(b));
    return r;
}
__device__ __forceinline__ u64 fmax2(u64 a, u64 b, u64 c) {
    u64 r;
    asm("fma.rn.f32x2 %0, %1, %2, %3;" : "=l"(r) : "l"(a), "l"(b), "l"(c));
    return r;
}
__device__ __forceinline__ float2 unpack2(u64 v) {
    float2 r;
    asm("mov.b64 {%0, %1}, %2;" : "=f"(r.x), "=f"(r.y) : "l"(v));
    return r;
}

// grid (8 j-tiles, 16 n), 512 threads = 16 warps (4/SMSP, 128-reg budget).
// Warp w: i-rows [16w, 16w+16). Lane: column j = jt*32 + lane.
// xi comes from GMEM via warp-uniform LDG.128 (L1 broadcast dedups — no smem
// crossbar); smem holds only the 32 columns of -y_j = -(xm*a) for this tile.
// Math: d = fma.f32x2(xi_raw, a_pair, -y_j); |d| via LOP3; tree addx2.
extern "C" __global__ void __launch_bounds__(512, 1)
fused_kernel(const float* __restrict__ x, const float* __restrict__ a,
             float* __restrict__ out) {
    __shared__ __align__(16) float yt[32 * YTS];   // -y for this tile's 32 cols
    __shared__ float red[512];                     // Sx partials, then colsums
    __shared__ float sqw[16];
    __shared__ float cs[32];
    __shared__ float wsum[16];

    const int tid  = threadIdx.x;
    const int lane = tid & 31;
    const int w    = tid >> 5;
    const int n    = blockIdx.y;
    const int jt   = blockIdx.x;
    const float* __restrict__ xm = x + (size_t)(n * TT + TT / 2) * (VV * FF);

    // Full xm scan: warms L1 for the uniform xi LDGs and yields dloss sums.
    float Sx = 0.f, Sq = 0.f;
#pragma unroll
    for (int k = 0; k < 32; ++k) {
        float v = __ldg(&xm[tid + (k << 9)]);      // f = tid&63 fixed per thread
        Sx += v;
        Sq = fmaf(v, v, Sq);
    }
    red[tid] = Sx;
#pragma unroll
    for (int o = 16; o; o >>= 1) Sq += __shfl_down_sync(~0u, Sq, o);
    if (lane == 0) sqw[w] = Sq;

    // Stage -y_j for this block's 32 columns (2048 values, 4/thread).
#pragma unroll
    for (int t = 0; t < 4; ++t) {
        int idx = tid + (t << 9);
        int c   = idx >> 6;
        int ff  = idx & 63;
        yt[c * YTS + ff] = -xm[(jt * 32 + c) * FF + ff] * __ldg(&a[ff]);
    }
    __syncthreads();

    // dloss_n = 2*(V*sum x^2 - sum_f (sum_i x)^2); valid because S's column
    // sums are exactly 1 (softmax axis) so sum(S@d2) == sum(d2).
    if (jt == 0 && w == 0) {
        float s1 = 0.f, s2 = 0.f;
#pragma unroll
        for (int r = 0; r < 8; ++r) {
            s1 += red[lane + (r << 6)];
            s2 += red[lane + 32 + (r << 6)];
        }
        float t  = s1 * s1 + s2 * s2;
        float sq = (lane < 16) ? sqw[lane] : 0.f;
#pragma unroll
        for (int o = 16; o; o >>= 1) {
            t  += __shfl_down_sync(~0u, t, o);
            sq += __shfl_down_sync(~0u, sq, o);
        }
        if (lane == 0) __stcg(&g_dloss[n], 2.f * ((float)VV * sq - t));
    }

    const float* __restrict__ yj = &yt[lane * YTS];       // this lane's -y_j
    const float* __restrict__ xib = xm + (w << 4) * FF;   // warp's 16 rows
    const u64 M = 0x7fffffff7fffffffULL;

    u64 acc[16];
#pragma unroll
    for (int g = 0; g < 16; ++g) acc[g] = 0;

#pragma unroll
    for (int h = 0; h < 4; ++h) {
        // a pairs for this 16-feature chunk (uniform LDG, 8 u64).
        u64 a2[8];
        {
            const ulonglong2* __restrict__ ap =
                reinterpret_cast<const ulonglong2*>(a + h * 16);
            ulonglong2 v0 = __ldg(ap), v1 = __ldg(ap + 1),
                       v2 = __ldg(ap + 2), v3 = __ldg(ap + 3);
            a2[0] = v0.x; a2[1] = v0.y; a2[2] = v1.x; a2[3] = v1.y;
            a2[4] = v2.x; a2[5] = v2.y; a2[6] = v3.x; a2[7] = v3.y;
        }
        // -y_j chunk from smem (conflict-free LDS.128, 8 u64).
        u64 nyj[8];
        {
            const ulonglong2* __restrict__ p =
                reinterpret_cast<const ulonglong2*>(yj + h * 16);
            ulonglong2 v0 = p[0], v1 = p[1], v2 = p[2], v3 = p[3];
            nyj[0] = v0.x; nyj[1] = v0.y; nyj[2] = v1.x; nyj[3] = v1.y;
            nyj[4] = v2.x; nyj[5] = v2.y; nyj[6] = v3.x; nyj[7] = v3.y;
        }
#pragma unroll
        for (int g = 0; g < 16; ++g) {
            const ulonglong2* __restrict__ xi =
                reinterpret_cast<const ulonglong2*>(xib + g * FF + h * 16);
            ulonglong2 q0 = __ldg(xi);          // warp-uniform LDG.128 (L1-hit)
            ulonglong2 q1 = __ldg(xi + 1);
            ulonglong2 q2 = __ldg(xi + 2);
            ulonglong2 q3 = __ldg(xi + 3);
            u64 d0 = fmax2(q0.x, a2[0], nyj[0]) & M;   // a*xi - a*xj, |.|
            u64 d1 = fmax2(q0.y, a2[1], nyj[1]) & M;
            u64 d2 = fmax2(q1.x, a2[2], nyj[2]) & M;
            u64 d3 = fmax2(q1.y, a2[3], nyj[3]) & M;
            u64 d4 = fmax2(q2.x, a2[4], nyj[4]) & M;
            u64 d5 = fmax2(q2.y, a2[5], nyj[5]) & M;
            u64 d6 = fmax2(q3.x, a2[6], nyj[6]) & M;
            u64 d7 = fmax2(q3.y, a2[7], nyj[7]) & M;
            u64 t = addx2(addx2(addx2(d0, d1), addx2(d2, d3)),
                          addx2(addx2(d4, d5), addx2(d6, d7)));
            acc[g] = addx2(acc[g], t);
        }
    }

    // exp (scores >= 0 always: relu is identity) + column partials.
    float tmp[16];
    float colpart = 0.f;
#pragma unroll
    for (int g = 0; g < 16; ++g) {
        float2 u = unpack2(acc[g]);
        float e  = __expf(u.x + u.y);
        tmp[g] = e;
        colpart += e;
    }

    __syncthreads();                 // red[] reuse barrier
    red[tid] = colpart;
    __syncthreads();
    if (tid < 32) {
        float s = 0.f;
#pragma unroll
        for (int ww = 0; ww < 16; ++ww) s += red[ww * 32 + tid];
        cs[tid] = s;
    }
    __syncthreads();
    const float inv = 1.0f / cs[lane];

    // Write S (coalesced) + accumulate S^2.
    float sq2 = 0.f;
    float* ocol = out + (size_t)n * (VV * VV) + jt * 32 + lane;
#pragma unroll
    for (int g = 0; g < 16; ++g) {
        float Sv = tmp[g] * inv;
        ocol[(size_t)((w << 4) + g) * VV] = Sv;
        sq2 = fmaf(Sv, Sv, sq2);
    }
#pragma unroll
    for (int o = 16; o; o >>= 1) sq2 += __shfl_down_sync(~0u, sq2, o);
    if (lane == 0) wsum[w] = sq2;
    __syncthreads();

    // Last-block finalize (graph-safe: counter reset each call).
    __shared__ unsigned int s_flag;
    const int bid = n * 8 + jt;
    if (tid == 0) {
        float t = 0.f;
#pragma unroll
        for (int k = 0; k < 16; ++k) t += wsum[k];
        __stcg(&g_sloss[bid], t);
        __threadfence();
        unsigned int c = atomicAdd(&g_counter, 1u);
        s_flag = (c == NBLK - 1) ? 1u : 0u;
    }
    __syncthreads();
    if (s_flag && w == 0) {
        __threadfence();
        float s = 0.f;
#pragma unroll
        for (int k = 0; k < 4; ++k) s += __ldcg(&g_sloss[lane + (k << 5)]);
        float dl = (lane < 16) ? __ldcg(&g_dloss[lane]) : 0.f;
#pragma unroll
        for (int o = 16; o; o >>= 1) {
            s  += __shfl_down_sync(~0u, s, o);
            dl += __shfl_down_sync(~0u, dl, o);
        }
        if (lane == 0) {
            out[NVV]     = s * (ALPHA_ / (float)NN);
            out[NVV + 1] = dl * ALPHA_;
            g_counter = 0;
        }
    }
}

extern "C" void kernel_launch(void* const* d_in, const int* in_sizes, int n_in,
                              void* d_out, int out_size) {
    const float* x = (const float*)d_in[0];
    const float* a = (const float*)d_in[1];
    if (n_in >= 2 && in_sizes[0] == FF) {      // defensive input-order check
        const float* t = x; x = a; a = t;
    }
    float* out = (float*)d_out;
    fused_kernel<<<dim3(8, NN), 512>>>(x, a, out);
}

// round 6
// speedup vs baseline: 1.1345x; 1.1345x over previous
#include <cuda_runtime.h>
#include <cstddef>

#define ALPHA_ 0.0001f
#define NN 16
#define TT 8
#define VV 256
#define FF 64
#define NVV (NN*VV*VV)
#define YS 68               // row stride (floats) = 272B == 16 mod 128 -> spreads bank quads
#define NBLK 128

__device__ float g_sloss[NBLK];
__device__ float g_dloss[NN];
__device__ unsigned int g_counter = 0;

typedef unsigned long long u64;

__device__ __forceinline__ u64 addx2(u64 a, u64 b) {
    u64 r;
    asm("add.rn.f32x2 %0, %1, %2;" : "=l"(r) : "l"(a), "l"(b));
    return r;
}
__device__ __forceinline__ float2 unpack2(u64 v) {
    float2 r;
    asm("mov.b64 {%0, %1}, %2;" : "=f"(r.x), "=f"(r.y) : "l"(v));
    return r;
}

// grid (8 j-tiles, 16 n), 512 threads = 16 warps.
// Warp w: i-band = (w>>1)*32, j-half = (w&1)*16. Lane: li=lane&7, lj=lane>>3.
// Thread tile: 4 i-rows (li+8k) x 4 j-cols (lj+4m) -> 16 packed accumulators.
// ALL smem loads are lane-distinct .128 (xi: 8 unique addrs/warp, xj: 4) ->
// 1 wavefront each, full crossbar utilization (fixes the uniform-load plateau).
extern "C" __global__ void __launch_bounds__(512)
fused_kernel(const float* __restrict__ x, const float* __restrict__ a,
             float* __restrict__ out) {
    extern __shared__ float sm[];
    float* y  = sm;                 // [256][YS]  y = xm * a
    float* ny = sm + VV * YS;       // [32][YS]   -y for this block's j-tile
    __shared__ float red[512];
    __shared__ float sqw[16];
    __shared__ float part[8][32];
    __shared__ float invs[32];
    __shared__ float wsum[16];

    const int tid   = threadIdx.x;
    const int lane  = tid & 31;
    const int w     = tid >> 5;
    const int iband = (w >> 1) * 32;
    const int jhalf = (w & 1) * 16;
    const int li    = lane & 7;
    const int lj    = lane >> 3;
    const int n     = blockIdx.y;
    const int jt    = blockIdx.x;
    const float* __restrict__ xm = x + (size_t)(n * TT + TT / 2) * (VV * FF);

    // Stage y = xm * a (tid&63 = fixed feature -> free per-f raw sums for dloss).
    const int   f  = tid & 63;
    const float af = __ldg(&a[f]);
    float Sx = 0.f, Sq = 0.f;
#pragma unroll
    for (int k = 0; k < 32; ++k) {
        int idx = tid + (k << 9);
        float v = xm[idx];
        y[(idx >> 6) * YS + f] = v * af;
        Sx += v;
        Sq = fmaf(v, v, Sq);
    }
    red[tid] = Sx;
#pragma unroll
    for (int o = 16; o; o >>= 1) Sq += __shfl_down_sync(~0u, Sq, o);
    if (lane == 0) sqw[w] = Sq;

    // Stage -y for this block's 32 j-columns (2048 elems, 4/thread).
#pragma unroll
    for (int t = 0; t < 4; ++t) {
        int idx = tid + (t << 9);
        int c   = idx >> 6;
        int ff  = idx & 63;
        ny[c * YS + ff] = -xm[(jt * 32 + c) * FF + ff] * __ldg(&a[ff]);
    }
    __syncthreads();

    // dloss_n = 2*(V*sum x^2 - sum_f (sum_i x)^2); valid because S's column
    // sums are exactly 1 (softmax axis) so sum(S@d2) == sum(d2).
    if (jt == 0 && w == 0) {
        float s1 = 0.f, s2 = 0.f;
#pragma unroll
        for (int r = 0; r < 8; ++r) {
            s1 += red[lane + (r << 6)];
            s2 += red[lane + 32 + (r << 6)];
        }
        float t  = s1 * s1 + s2 * s2;
        float sq = (lane < 16) ? sqw[lane] : 0.f;
#pragma unroll
        for (int o = 16; o; o >>= 1) {
            t  += __shfl_down_sync(~0u, t, o);
            sq += __shfl_down_sync(~0u, sq, o);
        }
        if (lane == 0) __stcg(&g_dloss[n], 2.f * ((float)VV * sq - t));
    }

    const float* __restrict__ yb  = y  + (iband + li) * YS;   // + k*8*YS + h*4
    const float* __restrict__ nyb = ny + (jhalf + lj) * YS;   // + m*4*YS + h*4
    const u64 M = 0x7fffffff7fffffffULL;

    u64 acc[16];
#pragma unroll
    for (int p = 0; p < 16; ++p) acc[p] = 0;

#pragma unroll 4
    for (int h = 0; h < 16; ++h) {
        ulonglong2 xi[4], xj[4];
#pragma unroll
        for (int k = 0; k < 4; ++k)
            xi[k] = *reinterpret_cast<const ulonglong2*>(yb + k * 8 * YS + h * 4);
#pragma unroll
        for (int m = 0; m < 4; ++m)
            xj[m] = *reinterpret_cast<const ulonglong2*>(nyb + m * 4 * YS + h * 4);
#pragma unroll
        for (int k = 0; k < 4; ++k)
#pragma unroll
            for (int m = 0; m < 4; ++m) {
                u64 d0 = addx2(xi[k].x, xj[m].x) & M;   // |y_i - y_j| packed
                u64 d1 = addx2(xi[k].y, xj[m].y) & M;
                acc[k * 4 + m] = addx2(acc[k * 4 + m], addx2(d0, d1));
            }
    }

    // exp (scores >= 0 so relu is identity) + per-thread j-partials.
    float e[16];
    float cp0 = 0.f, cp1 = 0.f, cp2 = 0.f, cp3 = 0.f;
#pragma unroll
    for (int k = 0; k < 4; ++k) {
#pragma unroll
        for (int m = 0; m < 4; ++m) {
            float2 u = unpack2(acc[k * 4 + m]);
            float v  = __expf(u.x + u.y);
            e[k * 4 + m] = v;
            if (m == 0) cp0 += v; else if (m == 1) cp1 += v;
            else if (m == 2) cp2 += v; else cp3 += v;
        }
    }
    // Reduce over li within each 8-lane group (same j-set).
#pragma unroll
    for (int o = 4; o; o >>= 1) {
        cp0 += __shfl_down_sync(~0u, cp0, o);
        cp1 += __shfl_down_sync(~0u, cp1, o);
        cp2 += __shfl_down_sync(~0u, cp2, o);
        cp3 += __shfl_down_sync(~0u, cp3, o);
    }
    if (li == 0) {
        part[iband >> 5][jhalf + lj]      = cp0;
        part[iband >> 5][jhalf + lj + 4]  = cp1;
        part[iband >> 5][jhalf + lj + 8]  = cp2;
        part[iband >> 5][jhalf + lj + 12] = cp3;
    }
    __syncthreads();
    if (tid < 32) {
        float s = 0.f;
#pragma unroll
        for (int b = 0; b < 8; ++b) s += part[b][tid];
        invs[tid] = 1.0f / s;
    }
    __syncthreads();

    float iv[4];
#pragma unroll
    for (int m = 0; m < 4; ++m) iv[m] = invs[jhalf + lj + 4 * m];

    // Write S + accumulate S^2.
    float sq2 = 0.f;
    float* ob = out + (size_t)n * (VV * VV) + jt * 32 + jhalf + lj;
#pragma unroll
    for (int k = 0; k < 4; ++k) {
        const size_t ro = (size_t)(iband + li + 8 * k) * VV;
#pragma unroll
        for (int m = 0; m < 4; ++m) {
            float Sv = e[k * 4 + m] * iv[m];
            ob[ro + 4 * m] = Sv;
            sq2 = fmaf(Sv, Sv, sq2);
        }
    }
#pragma unroll
    for (int o = 16; o; o >>= 1) sq2 += __shfl_down_sync(~0u, sq2, o);
    if (lane == 0) wsum[w] = sq2;
    __syncthreads();

    // Last-block finalize (graph-safe: counter reset each call).
    __shared__ unsigned int s_flag;
    const int bid = n * 8 + jt;
    if (tid == 0) {
        float t = 0.f;
#pragma unroll
        for (int k = 0; k < 16; ++k) t += wsum[k];
        __stcg(&g_sloss[bid], t);
        __threadfence();
        unsigned int c = atomicAdd(&g_counter, 1u);
        s_flag = (c == NBLK - 1) ? 1u : 0u;
    }
    __syncthreads();
    if (s_flag && w == 0) {
        __threadfence();
        float s = 0.f;
#pragma unroll
        for (int k = 0; k < 4; ++k) s += __ldcg(&g_sloss[lane + (k << 5)]);
        float dl = (lane < 16) ? __ldcg(&g_dloss[lane]) : 0.f;
#pragma unroll
        for (int o = 16; o; o >>= 1) {
            s  += __shfl_down_sync(~0u, s, o);
            dl += __shfl_down_sync(~0u, dl, o);
        }
        if (lane == 0) {
            out[NVV]     = s * (ALPHA_ / (float)NN);
            out[NVV + 1] = dl * ALPHA_;
            g_counter = 0;
        }
    }
}

extern "C" void kernel_launch(void* const* d_in, const int* in_sizes, int n_in,
                              void* d_out, int out_size) {
    const float* x = (const float*)d_in[0];
    const float* a = (const float*)d_in[1];
    if (n_in >= 2 && in_sizes[0] == FF) {      // defensive input-order check
        const float* t = x; x = a; a = t;
    }
    float* out = (float*)d_out;

    const int smem = (VV * YS + 32 * YS) * (int)sizeof(float);
    cudaFuncSetAttribute(fused_kernel,
                         cudaFuncAttributeMaxDynamicSharedMemorySize, smem);
    fused_kernel<<<dim3(8, NN), 512, smem>>>(x, a, out);
}